// round 2
// baseline (speedup 1.0000x reference)
#include <cuda_runtime.h>
#include <cstdint>

#define NN      50000
#define EE      800000
#define EP      850000      // EE + NN self loops
#define NG      50
#define DH      128

// ---------------- scratch (device globals; no allocation allowed) ----------
__device__ float g_feat[NN * DH];   // GEMM output h for current layer
__device__ float g_out [NN * DH];   // aggregation output (becomes next input)
__device__ float g_als [NN * 2];
__device__ float g_ald [NN * 2];
__device__ float g_e   [EP * 2];
__device__ float g_emax[NN * 2];
__device__ float g_den [NN * 2];
__device__ int   g_src [EP];
__device__ int   g_dst [EP];
__device__ float g_pool[NG * DH];
__device__ float g_cnt [NG];

// ---------------- helpers ---------------------------------------------------
__device__ __forceinline__ void atomicMaxF(float* addr, float v) {
    if (v >= 0.0f) atomicMax((int*)addr, __float_as_int(v));
    else           atomicMin((unsigned int*)addr, __float_as_uint(v));
}

__device__ __forceinline__ void redAddV4(float* p, float a, float b, float c, float d) {
    asm volatile("red.global.add.v4.f32 [%0], {%1,%2,%3,%4};"
                 :: "l"(p), "f"(a), "f"(b), "f"(c), "f"(d) : "memory");
}

// ---------------- edge-list int32 -> scratch (+ self loops) -----------------
__global__ void k_edges(const int* __restrict__ ei) {
    int i = blockIdx.x * blockDim.x + threadIdx.x;
    if (i >= EP) return;
    if (i < EE) { g_src[i] = ei[i]; g_dst[i] = ei[EE + i]; }
    else        { g_src[i] = i - EE; g_dst[i] = i - EE; }
}

// ---------------- SGEMM: [NN x 128] @ [128 x 128] -> g_feat -----------------
// Block tile 64 rows x 128 cols, BK=16, 256 threads, 8x4 micro-tile.
__global__ void k_gemm(const float* __restrict__ Aext, const float* __restrict__ W) {
    const float* A = Aext ? Aext : g_out;
    __shared__ float xs[16][68];    // padded; transposed [k][row]
    __shared__ float ws[16][128];
    int bm  = blockIdx.x * 64;
    int tid = threadIdx.x;
    int cg  = tid & 31;             // col group -> cols cg*4..cg*4+3
    int rg  = tid >> 5;             // row group -> rows rg*8..rg*8+7

    float acc[8][4];
#pragma unroll
    for (int r = 0; r < 8; r++)
#pragma unroll
        for (int c = 0; c < 4; c++) acc[r][c] = 0.0f;

    for (int k0 = 0; k0 < 128; k0 += 16) {
        // load x tile (64 rows x 16 k), transposed into xs
        {
            int r   = tid >> 2;            // 0..63
            int kk4 = (tid & 3) * 4;       // 0,4,8,12
            int row = bm + r;
            float4 v = make_float4(0.f, 0.f, 0.f, 0.f);
            if (row < NN) v = *(const float4*)(A + (size_t)row * 128 + k0 + kk4);
            xs[kk4 + 0][r] = v.x; xs[kk4 + 1][r] = v.y;
            xs[kk4 + 2][r] = v.z; xs[kk4 + 3][r] = v.w;
        }
        // load W tile (16 x 128) straight
        {
            const float4* Wp = (const float4*)(W + (size_t)k0 * 128);
            float4* wsp = (float4*)&ws[0][0];
            wsp[tid * 2 + 0] = Wp[tid * 2 + 0];
            wsp[tid * 2 + 1] = Wp[tid * 2 + 1];
        }
        __syncthreads();
#pragma unroll
        for (int kk = 0; kk < 16; kk++) {
            float a[8], b[4];
            *(float4*)(a)     = *(float4*)&xs[kk][rg * 8];
            *(float4*)(a + 4) = *(float4*)&xs[kk][rg * 8 + 4];
            *(float4*)(b)     = *(float4*)&ws[kk][cg * 4];
#pragma unroll
            for (int r = 0; r < 8; r++)
#pragma unroll
                for (int c = 0; c < 4; c++) acc[r][c] = fmaf(a[r], b[c], acc[r][c]);
        }
        __syncthreads();
    }
#pragma unroll
    for (int r = 0; r < 8; r++) {
        int row = bm + rg * 8 + r;
        if (row < NN) {
            float4 v = make_float4(acc[r][0], acc[r][1], acc[r][2], acc[r][3]);
            *(float4*)(g_feat + (size_t)row * 128 + cg * 4) = v;
        }
    }
}

// ---------------- attention logits: al_s/al_d per node (warp per node) ------
__global__ void k_al(const float* __restrict__ a_s, const float* __restrict__ a_d) {
    int gt   = blockIdx.x * blockDim.x + threadIdx.x;
    int node = gt >> 5;
    int lane = gt & 31;
    if (node >= NN) return;
    float4 hv = *(const float4*)(g_feat + (size_t)node * 128 + lane * 4);
    float4 sv = *(const float4*)(a_s + lane * 4);
    float4 dv = *(const float4*)(a_d + lane * 4);
    float s = hv.x * sv.x + hv.y * sv.y + hv.z * sv.z + hv.w * sv.w;
    float d = hv.x * dv.x + hv.y * dv.y + hv.z * dv.z + hv.w * dv.w;
#pragma unroll
    for (int off = 8; off > 0; off >>= 1) {
        s += __shfl_down_sync(0xffffffffu, s, off, 16);
        d += __shfl_down_sync(0xffffffffu, d, off, 16);
    }
    if ((lane & 15) == 0) {
        int head = lane >> 4;
        g_als[node * 2 + head] = s;
        g_ald[node * 2 + head] = d;
    }
}

// ---------------- init softmax state ----------------------------------------
__global__ void k_init_sm() {
    int i = blockIdx.x * blockDim.x + threadIdx.x;
    if (i < NN * 2) { g_emax[i] = __int_as_float(0xff800000); g_den[i] = 0.0f; }
}

__global__ void k_zero_out() {
    int i = blockIdx.x * blockDim.x + threadIdx.x;
    if (i < NN * 32) ((float4*)g_out)[i] = make_float4(0.f, 0.f, 0.f, 0.f);
}

__global__ void k_zero_pool() {
    int i = blockIdx.x * blockDim.x + threadIdx.x;
    if (i < NG * DH) g_pool[i] = 0.0f;
    if (i < NG)      g_cnt[i]  = 0.0f;
}

// ---------------- edge pass A: e = leaky_relu(al_s[src]+al_d[dst]); max -----
__global__ void k_passA() {
    int i = blockIdx.x * blockDim.x + threadIdx.x;
    if (i >= EP) return;
    int s = g_src[i], d = g_dst[i];
#pragma unroll
    for (int h = 0; h < 2; h++) {
        float e = g_als[s * 2 + h] + g_ald[d * 2 + h];
        e = (e > 0.0f) ? e : 0.2f * e;
        g_e[i * 2 + h] = e;
        atomicMaxF(&g_emax[d * 2 + h], e);
    }
}

// ---------------- edge pass B: exp(e - max); denominator --------------------
__global__ void k_passB() {
    int i = blockIdx.x * blockDim.x + threadIdx.x;
    if (i >= EP) return;
    int d = g_dst[i];
    float e0 = __expf(g_e[i * 2 + 0] - g_emax[d * 2 + 0]);
    float e1 = __expf(g_e[i * 2 + 1] - g_emax[d * 2 + 1]);
    g_e[i * 2 + 0] = e0;
    g_e[i * 2 + 1] = e1;
    atomicAdd(&g_den[d * 2 + 0], e0);
    atomicAdd(&g_den[d * 2 + 1], e1);
}

// ---------------- edge pass C: out[dst] += alpha * h[src] (warp per edge) ---
__global__ void k_passC() {
    int gt   = blockIdx.x * blockDim.x + threadIdx.x;
    int i    = gt >> 5;
    int lane = gt & 31;
    if (i >= EP) return;
    int s = g_src[i], d = g_dst[i];
    int head = lane >> 4;
    float alpha = g_e[i * 2 + head] / (g_den[d * 2 + head] + 1e-16f);
    float4 hv = *(const float4*)(g_feat + (size_t)s * 128 + lane * 4);
    float* dst = g_out + (size_t)d * 128 + lane * 4;
    redAddV4(dst, hv.x * alpha, hv.y * alpha, hv.z * alpha, hv.w * alpha);
}

// ---------------- relu(out + bias) in place ---------------------------------
__global__ void k_relu_bias(const float* __restrict__ bias) {
    int i = blockIdx.x * blockDim.x + threadIdx.x;
    if (i >= NN * 32) return;
    int c4 = i & 31;
    float4 v  = ((float4*)g_out)[i];
    float4 bv = ((const float4*)bias)[c4];
    v.x = fmaxf(v.x + bv.x, 0.f); v.y = fmaxf(v.y + bv.y, 0.f);
    v.z = fmaxf(v.z + bv.z, 0.f); v.w = fmaxf(v.w + bv.w, 0.f);
    ((float4*)g_out)[i] = v;
}

// ---------------- fused relu+bias + mean-pool accumulation ------------------
__global__ void k_pool(const int* __restrict__ batch, const float* __restrict__ bias) {
    int i = blockIdx.x * blockDim.x + threadIdx.x;
    if (i >= NN * 32) return;
    int n  = i >> 5;
    int c4 = i & 31;
    int g  = batch[n];
    float4 v  = ((float4*)g_out)[i];
    float4 bv = ((const float4*)bias)[c4];
    v.x = fmaxf(v.x + bv.x, 0.f); v.y = fmaxf(v.y + bv.y, 0.f);
    v.z = fmaxf(v.z + bv.z, 0.f); v.w = fmaxf(v.w + bv.w, 0.f);
    redAddV4(g_pool + g * 128 + c4 * 4, v.x, v.y, v.z, v.w);
    if (c4 == 0) atomicAdd(&g_cnt[g], 1.0f);
}

// ---------------- head: (pooled / count) @ Wh + bh --------------------------
__global__ void k_head(const float* __restrict__ Wh, const float* __restrict__ bh,
                       float* __restrict__ out) {
    int g = blockIdx.x;
    int t = threadIdx.x;                 // 128 threads
    float denom = fmaxf(g_cnt[g], 1.0f);
    float v = (g_pool[g * 128 + t] / denom) * Wh[t];
    __shared__ float sred[4];
#pragma unroll
    for (int off = 16; off > 0; off >>= 1) v += __shfl_down_sync(0xffffffffu, v, off);
    if ((t & 31) == 0) sred[t >> 5] = v;
    __syncthreads();
    if (t == 0) out[g] = sred[0] + sred[1] + sred[2] + sred[3] + bh[0];
}

// ---------------- launch ----------------------------------------------------
extern "C" void kernel_launch(void* const* d_in, const int* in_sizes, int n_in,
                              void* d_out, int out_size) {
    const float* x     = (const float*)d_in[0];
    const int*   ei    = (const int*)d_in[1];     // int32 (JAX demotes int64)
    const int*   batch = (const int*)d_in[2];     // int32
    const float* W1    = (const float*)d_in[3];
    const float* as1   = (const float*)d_in[4];
    const float* ad1   = (const float*)d_in[5];
    const float* b1    = (const float*)d_in[6];
    const float* W2    = (const float*)d_in[7];
    const float* as2   = (const float*)d_in[8];
    const float* ad2   = (const float*)d_in[9];
    const float* b2    = (const float*)d_in[10];
    const float* Wh    = (const float*)d_in[11];
    const float* bh    = (const float*)d_in[12];
    float* out = (float*)d_out;

    const int TB = 256;
    int grid_edges = (EP + TB - 1) / TB;             // 3321
    int grid_gemm  = (NN + 63) / 64;                 // 782
    int grid_warpN = (NN * 32 + TB - 1) / TB;        // 6250
    int grid_sm    = (NN * 2 + TB - 1) / TB;         // 391
    int grid_v4    = (NN * 32 + TB - 1) / TB;        // 6250
    int grid_passC = (EP * 32 + TB - 1) / TB;        // 106250

    k_edges<<<grid_edges, TB>>>(ei);

    // ---- layer 1 ----
    k_gemm<<<grid_gemm, TB>>>(x, W1);
    k_al<<<grid_warpN, TB>>>(as1, ad1);
    k_init_sm<<<grid_sm, TB>>>();
    k_zero_out<<<grid_v4, TB>>>();
    k_passA<<<grid_edges, TB>>>();
    k_passB<<<grid_edges, TB>>>();
    k_passC<<<grid_passC, TB>>>();
    k_relu_bias<<<grid_v4, TB>>>(b1);

    // ---- layer 2 (GEMM consumes g_out, then g_out is recycled) ----
    k_gemm<<<grid_gemm, TB>>>(nullptr, W2);
    k_al<<<grid_warpN, TB>>>(as2, ad2);
    k_init_sm<<<grid_sm, TB>>>();
    k_zero_out<<<grid_v4, TB>>>();
    k_passA<<<grid_edges, TB>>>();
    k_passB<<<grid_edges, TB>>>();
    k_passC<<<grid_passC, TB>>>();

    // ---- pool + head ----
    k_zero_pool<<<(NG * DH + TB - 1) / TB, TB>>>();
    k_pool<<<grid_v4, TB>>>(batch, b2);
    k_head<<<NG, 128>>>(Wh, bh, out);
}

// round 3
// speedup vs baseline: 1.9186x; 1.9186x over previous
#include <cuda_runtime.h>
#include <cstdint>

#define NN      50000
#define EE      800000
#define EP      850000      // EE + NN self loops
#define NG      50
#define DH      128
#define NBLK_SCAN 49        // ceil(NN/1024)

// ---------------- scratch (device globals) ----------------------------------
__device__ float g_feat[NN * DH];   // GEMM output h for current layer
__device__ float g_out [NN * DH];   // layer-1 aggregation output (layer-2 input)
__device__ float g_als [NN * 2];
__device__ float g_ald [NN * 2];
__device__ int   g_cntdeg[NN];      // in-degree histogram
__device__ int   g_tmp   [NN];      // inclusive scan scratch
__device__ int   g_bsum  [NBLK_SCAN];
__device__ int   g_boff  [NBLK_SCAN];
__device__ int   g_rowptr[NN + 1];
__device__ int   g_cursor[NN];
__device__ int   g_esrc  [EP];      // src node per CSR slot
__device__ float g_pool[NG * DH];
__device__ float g_cnt [NG];

__device__ __forceinline__ void redAddV4(float* p, float a, float b, float c, float d) {
    asm volatile("red.global.add.v4.f32 [%0], {%1,%2,%3,%4};"
                 :: "l"(p), "f"(a), "f"(b), "f"(c), "f"(d) : "memory");
}

// ---------------- CSR build --------------------------------------------------
__global__ void k_zero_init() {
    int i = blockIdx.x * blockDim.x + threadIdx.x;
    if (i < NN) g_cntdeg[i] = 0;
    if (i < NG * DH) g_pool[i] = 0.0f;
    if (i < NG) g_cnt[i] = 0.0f;
}

__global__ void k_hist(const int* __restrict__ ei) {
    int e = blockIdx.x * blockDim.x + threadIdx.x;
    if (e >= EP) return;
    int d = (e < EE) ? ei[EE + e] : (e - EE);
    atomicAdd(&g_cntdeg[d], 1);
}

__global__ void k_scan1() {            // 49 blocks x 1024: inclusive scan per block
    __shared__ int s[1024];
    int t = threadIdx.x;
    int i = blockIdx.x * 1024 + t;
    int v = (i < NN) ? g_cntdeg[i] : 0;
    s[t] = v;
    __syncthreads();
#pragma unroll
    for (int off = 1; off < 1024; off <<= 1) {
        int add = (t >= off) ? s[t - off] : 0;
        __syncthreads();
        s[t] += add;
        __syncthreads();
    }
    if (i < NN) g_tmp[i] = s[t];
    if (t == 1023) g_bsum[blockIdx.x] = s[t];
}

__global__ void k_scan2() {            // 1 thread: scan 49 block sums
    if (threadIdx.x == 0) {
        int run = 0;
        for (int b = 0; b < NBLK_SCAN; b++) { g_boff[b] = run; run += g_bsum[b]; }
    }
}

__global__ void k_scan3() {
    int i = blockIdx.x * blockDim.x + threadIdx.x;
    if (i >= NN) return;
    int incl = g_tmp[i] + g_boff[i >> 10];
    g_rowptr[i + 1] = incl;
    g_cursor[i]     = incl - g_cntdeg[i];
    if (i == 0) g_rowptr[0] = 0;
}

__global__ void k_scatter(const int* __restrict__ ei) {
    int e = blockIdx.x * blockDim.x + threadIdx.x;
    if (e >= EP) return;
    int s, d;
    if (e < EE) { s = ei[e]; d = ei[EE + e]; }
    else        { s = d = e - EE; }
    int pos = atomicAdd(&g_cursor[d], 1);
    g_esrc[pos] = s;
}

// ---------------- SGEMM + fused attention-logit epilogue --------------------
// [NN x 128] @ [128 x 128] -> g_feat ; al_s/al_d per row via warp reduction.
__global__ void k_gemm(const float* __restrict__ Aext, const float* __restrict__ W,
                       const float* __restrict__ a_s, const float* __restrict__ a_d) {
    const float* A = Aext ? Aext : g_out;
    __shared__ float xs[16][68];
    __shared__ float ws[16][128];
    int bm  = blockIdx.x * 64;
    int tid = threadIdx.x;
    int cg  = tid & 31;
    int rg  = tid >> 5;

    float acc[8][4];
#pragma unroll
    for (int r = 0; r < 8; r++)
#pragma unroll
        for (int c = 0; c < 4; c++) acc[r][c] = 0.0f;

    for (int k0 = 0; k0 < 128; k0 += 16) {
        {
            int r   = tid >> 2;
            int kk4 = (tid & 3) * 4;
            int row = bm + r;
            float4 v = make_float4(0.f, 0.f, 0.f, 0.f);
            if (row < NN) v = *(const float4*)(A + (size_t)row * 128 + k0 + kk4);
            xs[kk4 + 0][r] = v.x; xs[kk4 + 1][r] = v.y;
            xs[kk4 + 2][r] = v.z; xs[kk4 + 3][r] = v.w;
        }
        {
            const float4* Wp = (const float4*)(W + (size_t)k0 * 128);
            float4* wsp = (float4*)&ws[0][0];
            wsp[tid * 2 + 0] = Wp[tid * 2 + 0];
            wsp[tid * 2 + 1] = Wp[tid * 2 + 1];
        }
        __syncthreads();
#pragma unroll
        for (int kk = 0; kk < 16; kk++) {
            float a[8], b[4];
            *(float4*)(a)     = *(float4*)&xs[kk][rg * 8];
            *(float4*)(a + 4) = *(float4*)&xs[kk][rg * 8 + 4];
            *(float4*)(b)     = *(float4*)&ws[kk][cg * 4];
#pragma unroll
            for (int r = 0; r < 8; r++)
#pragma unroll
                for (int c = 0; c < 4; c++) acc[r][c] = fmaf(a[r], b[c], acc[r][c]);
        }
        __syncthreads();
    }

    const float4 asv = *(const float4*)(a_s + cg * 4);
    const float4 adv = *(const float4*)(a_d + cg * 4);
#pragma unroll
    for (int r = 0; r < 8; r++) {
        int row = bm + rg * 8 + r;
        float ps = acc[r][0]*asv.x + acc[r][1]*asv.y + acc[r][2]*asv.z + acc[r][3]*asv.w;
        float pd = acc[r][0]*adv.x + acc[r][1]*adv.y + acc[r][2]*adv.z + acc[r][3]*adv.w;
#pragma unroll
        for (int off = 8; off > 0; off >>= 1) {
            ps += __shfl_down_sync(0xffffffffu, ps, off, 16);
            pd += __shfl_down_sync(0xffffffffu, pd, off, 16);
        }
        if (row < NN) {
            if ((cg & 15) == 0) {
                int head = cg >> 4;
                g_als[row * 2 + head] = ps;
                g_ald[row * 2 + head] = pd;
            }
            float4 v = make_float4(acc[r][0], acc[r][1], acc[r][2], acc[r][3]);
            *(float4*)(g_feat + (size_t)row * 128 + cg * 4) = v;
        }
    }
}

// ---------------- fused softmax + aggregation (warp per dst) ----------------
// MODE 0: out = relu(agg + bias) -> g_out        (layer 1)
// MODE 1: relu(agg + bias) accumulated to pool   (layer 2)
template <int MODE>
__global__ void k_agg(const float* __restrict__ bias, const int* __restrict__ batch) {
    int gw   = (blockIdx.x * blockDim.x + threadIdx.x) >> 5;
    int lane = threadIdx.x & 31;
    if (gw >= NN) return;
    const int d    = gw;
    const int head = lane >> 4;
    const int beg  = g_rowptr[d];
    const int end  = g_rowptr[d + 1];

    const float2 aldv = *(const float2*)(g_ald + d * 2);

    // phase 1: per-head max over incoming edges
    float m0 = -3.402823466e38f, m1 = -3.402823466e38f;
    for (int i = beg + lane; i < end; i += 32) {
        float2 asv = *(const float2*)(g_als + g_esrc[i] * 2);
        float e0 = asv.x + aldv.x; e0 = (e0 > 0.f) ? e0 : 0.2f * e0;
        float e1 = asv.y + aldv.y; e1 = (e1 > 0.f) ? e1 : 0.2f * e1;
        m0 = fmaxf(m0, e0); m1 = fmaxf(m1, e1);
    }
#pragma unroll
    for (int off = 16; off > 0; off >>= 1) {
        m0 = fmaxf(m0, __shfl_xor_sync(0xffffffffu, m0, off));
        m1 = fmaxf(m1, __shfl_xor_sync(0xffffffffu, m1, off));
    }

    // phase 2: denominators
    float s0 = 0.f, s1 = 0.f;
    for (int i = beg + lane; i < end; i += 32) {
        float2 asv = *(const float2*)(g_als + g_esrc[i] * 2);
        float e0 = asv.x + aldv.x; e0 = (e0 > 0.f) ? e0 : 0.2f * e0;
        float e1 = asv.y + aldv.y; e1 = (e1 > 0.f) ? e1 : 0.2f * e1;
        s0 += __expf(e0 - m0); s1 += __expf(e1 - m1);
    }
#pragma unroll
    for (int off = 16; off > 0; off >>= 1) {
        s0 += __shfl_xor_sync(0xffffffffu, s0, off);
        s1 += __shfl_xor_sync(0xffffffffu, s1, off);
    }
    const float m_h   = head ? m1 : m0;
    const float inv_h = 1.0f / ((head ? s1 : s0) + 1e-16f);
    const float ald_h = head ? aldv.y : aldv.x;

    // phase 3: serial edge loop, 512B gather per edge across the warp
    float4 acc = make_float4(0.f, 0.f, 0.f, 0.f);
    for (int i = beg; i < end; i++) {
        int s = g_esrc[i];
        float e = g_als[s * 2 + head] + ald_h;
        e = (e > 0.f) ? e : 0.2f * e;
        float alpha = __expf(e - m_h) * inv_h;
        float4 hv = *(const float4*)(g_feat + (size_t)s * 128 + lane * 4);
        acc.x = fmaf(alpha, hv.x, acc.x);
        acc.y = fmaf(alpha, hv.y, acc.y);
        acc.z = fmaf(alpha, hv.z, acc.z);
        acc.w = fmaf(alpha, hv.w, acc.w);
    }

    const float4 bv = *(const float4*)(bias + lane * 4);
    acc.x = fmaxf(acc.x + bv.x, 0.f); acc.y = fmaxf(acc.y + bv.y, 0.f);
    acc.z = fmaxf(acc.z + bv.z, 0.f); acc.w = fmaxf(acc.w + bv.w, 0.f);

    if (MODE == 0) {
        *(float4*)(g_out + (size_t)d * 128 + lane * 4) = acc;
    } else {
        int g = batch[d];
        redAddV4(g_pool + g * 128 + lane * 4, acc.x, acc.y, acc.z, acc.w);
        if (lane == 0) atomicAdd(&g_cnt[g], 1.0f);
    }
}

// ---------------- head: (pooled / count) @ Wh + bh --------------------------
__global__ void k_head(const float* __restrict__ Wh, const float* __restrict__ bh,
                       float* __restrict__ out) {
    int g = blockIdx.x;
    int t = threadIdx.x;                 // 128 threads
    float denom = fmaxf(g_cnt[g], 1.0f);
    float v = (g_pool[g * 128 + t] / denom) * Wh[t];
    __shared__ float sred[4];
#pragma unroll
    for (int off = 16; off > 0; off >>= 1) v += __shfl_down_sync(0xffffffffu, v, off);
    if ((t & 31) == 0) sred[t >> 5] = v;
    __syncthreads();
    if (t == 0) out[g] = sred[0] + sred[1] + sred[2] + sred[3] + bh[0];
}

// ---------------- launch ----------------------------------------------------
extern "C" void kernel_launch(void* const* d_in, const int* in_sizes, int n_in,
                              void* d_out, int out_size) {
    const float* x     = (const float*)d_in[0];
    const int*   ei    = (const int*)d_in[1];
    const int*   batch = (const int*)d_in[2];
    const float* W1    = (const float*)d_in[3];
    const float* as1   = (const float*)d_in[4];
    const float* ad1   = (const float*)d_in[5];
    const float* b1    = (const float*)d_in[6];
    const float* W2    = (const float*)d_in[7];
    const float* as2   = (const float*)d_in[8];
    const float* ad2   = (const float*)d_in[9];
    const float* b2    = (const float*)d_in[10];
    const float* Wh    = (const float*)d_in[11];
    const float* bh    = (const float*)d_in[12];
    float* out = (float*)d_out;

    const int TB = 256;
    int grid_edges = (EP + TB - 1) / TB;
    int grid_nodes = (NN + TB - 1) / TB;
    int grid_gemm  = (NN + 63) / 64;
    int grid_agg   = (NN * 32 + TB - 1) / TB;

    // CSR build (reused by both layers)
    k_zero_init<<<grid_nodes, TB>>>();
    k_hist<<<grid_edges, TB>>>(ei);
    k_scan1<<<NBLK_SCAN, 1024>>>();
    k_scan2<<<1, 32>>>();
    k_scan3<<<grid_nodes, TB>>>();
    k_scatter<<<grid_edges, TB>>>(ei);

    // layer 1
    k_gemm<<<grid_gemm, TB>>>(x, W1, as1, ad1);
    k_agg<0><<<grid_agg, TB>>>(b1, batch);

    // layer 2
    k_gemm<<<grid_gemm, TB>>>(nullptr, W2, as2, ad2);
    k_agg<1><<<grid_agg, TB>>>(b2, batch);

    // head
    k_head<<<NG, 128>>>(Wh, bh, out);
}

// round 4
// speedup vs baseline: 1.9881x; 1.0362x over previous
#include <cuda_runtime.h>
#include <cstdint>

#define NN      50000
#define EE      800000
#define EP      850000      // EE + NN self loops
#define NG      50
#define DH      128
#define NBLK_SCAN 49        // ceil(NN/1024)

// ---------------- scratch (device globals) ----------------------------------
__device__ float g_feat[NN * DH];
__device__ float g_out [NN * DH];
__device__ float g_als [NN * 2];
__device__ float g_ald [NN * 2];
__device__ int   g_cntdeg[NN];
__device__ int   g_tmp   [NN];
__device__ int   g_bsum  [NBLK_SCAN];
__device__ int   g_boff  [NBLK_SCAN];
__device__ int   g_rowptr[NN + 1];
__device__ int   g_cursor[NN];
__device__ int   g_esrc  [EP];
__device__ float g_pool[NG * DH];
__device__ float g_cnt [NG];

__device__ __forceinline__ void redAddV4(float* p, float a, float b, float c, float d) {
    asm volatile("red.global.add.v4.f32 [%0], {%1,%2,%3,%4};"
                 :: "l"(p), "f"(a), "f"(b), "f"(c), "f"(d) : "memory");
}

// packed f32x2 helpers ---------------------------------------------------------
__device__ __forceinline__ unsigned long long pack2(float lo, float hi) {
    unsigned long long r;
    asm("mov.b64 %0, {%1,%2};" : "=l"(r) : "f"(lo), "f"(hi));
    return r;
}
__device__ __forceinline__ void fma2(unsigned long long& d,
                                     unsigned long long a, unsigned long long b) {
    asm("fma.rn.f32x2 %0, %1, %2, %0;" : "+l"(d) : "l"(a), "l"(b));
}
__device__ __forceinline__ void unpack2(float& lo, float& hi, unsigned long long v) {
    asm("mov.b64 {%0,%1}, %2;" : "=f"(lo), "=f"(hi) : "l"(v));
}

// ---------------- CSR build --------------------------------------------------
__global__ void k_zero_init() {
    int i = blockIdx.x * blockDim.x + threadIdx.x;
    if (i < NN) g_cntdeg[i] = 0;
    if (i < NG * DH) g_pool[i] = 0.0f;
    if (i < NG) g_cnt[i] = 0.0f;
}

__global__ void k_hist(const int* __restrict__ ei) {
    int e = blockIdx.x * blockDim.x + threadIdx.x;
    if (e >= EP) return;
    int d = (e < EE) ? ei[EE + e] : (e - EE);
    atomicAdd(&g_cntdeg[d], 1);
}

__global__ void k_scan1() {            // 49 blocks x 1024: inclusive scan per block
    __shared__ int s[1024];
    int t = threadIdx.x;
    int i = blockIdx.x * 1024 + t;
    int v = (i < NN) ? g_cntdeg[i] : 0;
    s[t] = v;
    __syncthreads();
#pragma unroll
    for (int off = 1; off < 1024; off <<= 1) {
        int add = (t >= off) ? s[t - off] : 0;
        __syncthreads();
        s[t] += add;
        __syncthreads();
    }
    if (i < NN) g_tmp[i] = s[t];
    if (t == 1023) g_bsum[blockIdx.x] = s[t];
}

__global__ void k_scan2() {            // 64 threads: parallel scan of 49 block sums
    __shared__ int s[64];
    int t = threadIdx.x;
    int v = (t < NBLK_SCAN) ? g_bsum[t] : 0;
    s[t] = v;
    __syncthreads();
#pragma unroll
    for (int off = 1; off < 64; off <<= 1) {
        int add = (t >= off) ? s[t - off] : 0;
        __syncthreads();
        s[t] += add;
        __syncthreads();
    }
    if (t < NBLK_SCAN) g_boff[t] = s[t] - v;   // exclusive
}

__global__ void k_scan3() {
    int i = blockIdx.x * blockDim.x + threadIdx.x;
    if (i >= NN) return;
    int incl = g_tmp[i] + g_boff[i >> 10];
    g_rowptr[i + 1] = incl;
    g_cursor[i]     = incl - g_cntdeg[i];
    if (i == 0) g_rowptr[0] = 0;
}

__global__ void k_scatter(const int* __restrict__ ei) {
    int e = blockIdx.x * blockDim.x + threadIdx.x;
    if (e >= EP) return;
    int s, d;
    if (e < EE) { s = ei[e]; d = ei[EE + e]; }
    else        { s = d = e - EE; }
    int pos = atomicAdd(&g_cursor[d], 1);
    g_esrc[pos] = s;
}

// ---------------- SGEMM (f32x2 packed) + fused attention-logit epilogue -----
__global__ void k_gemm(const float* __restrict__ Aext, const float* __restrict__ W,
                       const float* __restrict__ a_s, const float* __restrict__ a_d) {
    const float* A = Aext ? Aext : g_out;
    __shared__ float xs[16][68];    // transposed [k][row], row pairs contiguous
    __shared__ float ws[16][128];
    int bm  = blockIdx.x * 64;
    int tid = threadIdx.x;
    int cg  = tid & 31;             // cols cg*4..cg*4+3
    int rg  = tid >> 5;             // rows rg*8..rg*8+7

    // accumulators packed over row pairs: acc2[r2][c] = (acc[2r2][c], acc[2r2+1][c])
    unsigned long long acc2[4][4];
#pragma unroll
    for (int r2 = 0; r2 < 4; r2++)
#pragma unroll
        for (int c = 0; c < 4; c++) acc2[r2][c] = 0ull;

    for (int k0 = 0; k0 < 128; k0 += 16) {
        {
            int r   = tid >> 2;
            int kk4 = (tid & 3) * 4;
            int row = bm + r;
            float4 v = make_float4(0.f, 0.f, 0.f, 0.f);
            if (row < NN) v = *(const float4*)(A + (size_t)row * 128 + k0 + kk4);
            xs[kk4 + 0][r] = v.x; xs[kk4 + 1][r] = v.y;
            xs[kk4 + 2][r] = v.z; xs[kk4 + 3][r] = v.w;
        }
        {
            const float4* Wp = (const float4*)(W + (size_t)k0 * 128);
            float4* wsp = (float4*)&ws[0][0];
            wsp[tid * 2 + 0] = Wp[tid * 2 + 0];
            wsp[tid * 2 + 1] = Wp[tid * 2 + 1];
        }
        __syncthreads();
#pragma unroll
        for (int kk = 0; kk < 16; kk++) {
            float4 bq = *(float4*)&ws[kk][cg * 4];
            unsigned long long bb[4];
            bb[0] = pack2(bq.x, bq.x); bb[1] = pack2(bq.y, bq.y);
            bb[2] = pack2(bq.z, bq.z); bb[3] = pack2(bq.w, bq.w);
            const unsigned long long* ap =
                (const unsigned long long*)&xs[kk][rg * 8];
#pragma unroll
            for (int r2 = 0; r2 < 4; r2++) {
                unsigned long long aa = ap[r2];
                fma2(acc2[r2][0], aa, bb[0]);
                fma2(acc2[r2][1], aa, bb[1]);
                fma2(acc2[r2][2], aa, bb[2]);
                fma2(acc2[r2][3], aa, bb[3]);
            }
        }
        __syncthreads();
    }

    float acc[8][4];
#pragma unroll
    for (int r2 = 0; r2 < 4; r2++)
#pragma unroll
        for (int c = 0; c < 4; c++)
            unpack2(acc[2 * r2][c], acc[2 * r2 + 1][c], acc2[r2][c]);

    const float4 asv = *(const float4*)(a_s + cg * 4);
    const float4 adv = *(const float4*)(a_d + cg * 4);
#pragma unroll
    for (int r = 0; r < 8; r++) {
        int row = bm + rg * 8 + r;
        float ps = acc[r][0]*asv.x + acc[r][1]*asv.y + acc[r][2]*asv.z + acc[r][3]*asv.w;
        float pd = acc[r][0]*adv.x + acc[r][1]*adv.y + acc[r][2]*adv.z + acc[r][3]*adv.w;
#pragma unroll
        for (int off = 8; off > 0; off >>= 1) {
            ps += __shfl_down_sync(0xffffffffu, ps, off, 16);
            pd += __shfl_down_sync(0xffffffffu, pd, off, 16);
        }
        if (row < NN) {
            if ((cg & 15) == 0) {
                int head = cg >> 4;
                g_als[row * 2 + head] = ps;
                g_ald[row * 2 + head] = pd;
            }
            float4 v = make_float4(acc[r][0], acc[r][1], acc[r][2], acc[r][3]);
            *(float4*)(g_feat + (size_t)row * 128 + cg * 4) = v;
        }
    }
}

// ---------------- fused softmax + aggregation (warp per dst) ----------------
template <int MODE>
__global__ void k_agg(const float* __restrict__ bias, const int* __restrict__ batch) {
    int gw   = (blockIdx.x * blockDim.x + threadIdx.x) >> 5;
    int lane = threadIdx.x & 31;
    if (gw >= NN) return;
    const int d    = gw;
    const int head = lane >> 4;
    const int beg  = g_rowptr[d];
    const int end  = g_rowptr[d + 1];

    const float2 aldv = *(const float2*)(g_ald + d * 2);

    // phase 1: per-head max
    float m0 = -3.402823466e38f, m1 = -3.402823466e38f;
    for (int i = beg + lane; i < end; i += 32) {
        float2 asv = *(const float2*)(g_als + g_esrc[i] * 2);
        float e0 = asv.x + aldv.x; e0 = (e0 > 0.f) ? e0 : 0.2f * e0;
        float e1 = asv.y + aldv.y; e1 = (e1 > 0.f) ? e1 : 0.2f * e1;
        m0 = fmaxf(m0, e0); m1 = fmaxf(m1, e1);
    }
#pragma unroll
    for (int off = 16; off > 0; off >>= 1) {
        m0 = fmaxf(m0, __shfl_xor_sync(0xffffffffu, m0, off));
        m1 = fmaxf(m1, __shfl_xor_sync(0xffffffffu, m1, off));
    }

    // phase 2: denominators
    float s0 = 0.f, s1 = 0.f;
    for (int i = beg + lane; i < end; i += 32) {
        float2 asv = *(const float2*)(g_als + g_esrc[i] * 2);
        float e0 = asv.x + aldv.x; e0 = (e0 > 0.f) ? e0 : 0.2f * e0;
        float e1 = asv.y + aldv.y; e1 = (e1 > 0.f) ? e1 : 0.2f * e1;
        s0 += __expf(e0 - m0); s1 += __expf(e1 - m1);
    }
#pragma unroll
    for (int off = 16; off > 0; off >>= 1) {
        s0 += __shfl_xor_sync(0xffffffffu, s0, off);
        s1 += __shfl_xor_sync(0xffffffffu, s1, off);
    }
    const float m_h   = head ? m1 : m0;
    const float inv_h = 1.0f / ((head ? s1 : s0) + 1e-16f);
    const float ald_h = head ? aldv.y : aldv.x;

    // phase 3: serial edge loop, unrolled x2 for MLP
    float4 acc = make_float4(0.f, 0.f, 0.f, 0.f);
    int i = beg;
    for (; i + 2 <= end; i += 2) {
        int sA = g_esrc[i], sB = g_esrc[i + 1];
        float eA = g_als[sA * 2 + head] + ald_h;
        float eB = g_als[sB * 2 + head] + ald_h;
        eA = (eA > 0.f) ? eA : 0.2f * eA;
        eB = (eB > 0.f) ? eB : 0.2f * eB;
        float alA = __expf(eA - m_h) * inv_h;
        float alB = __expf(eB - m_h) * inv_h;
        float4 hA = *(const float4*)(g_feat + (size_t)sA * 128 + lane * 4);
        float4 hB = *(const float4*)(g_feat + (size_t)sB * 128 + lane * 4);
        acc.x = fmaf(alA, hA.x, acc.x); acc.y = fmaf(alA, hA.y, acc.y);
        acc.z = fmaf(alA, hA.z, acc.z); acc.w = fmaf(alA, hA.w, acc.w);
        acc.x = fmaf(alB, hB.x, acc.x); acc.y = fmaf(alB, hB.y, acc.y);
        acc.z = fmaf(alB, hB.z, acc.z); acc.w = fmaf(alB, hB.w, acc.w);
    }
    if (i < end) {
        int s = g_esrc[i];
        float e = g_als[s * 2 + head] + ald_h;
        e = (e > 0.f) ? e : 0.2f * e;
        float alpha = __expf(e - m_h) * inv_h;
        float4 hv = *(const float4*)(g_feat + (size_t)s * 128 + lane * 4);
        acc.x = fmaf(alpha, hv.x, acc.x); acc.y = fmaf(alpha, hv.y, acc.y);
        acc.z = fmaf(alpha, hv.z, acc.z); acc.w = fmaf(alpha, hv.w, acc.w);
    }

    const float4 bv = *(const float4*)(bias + lane * 4);
    acc.x = fmaxf(acc.x + bv.x, 0.f); acc.y = fmaxf(acc.y + bv.y, 0.f);
    acc.z = fmaxf(acc.z + bv.z, 0.f); acc.w = fmaxf(acc.w + bv.w, 0.f);

    if (MODE == 0) {
        *(float4*)(g_out + (size_t)d * 128 + lane * 4) = acc;
    } else {
        int g = batch[d];
        redAddV4(g_pool + g * 128 + lane * 4, acc.x, acc.y, acc.z, acc.w);
        if (lane == 0) atomicAdd(&g_cnt[g], 1.0f);
    }
}

// ---------------- head ------------------------------------------------------
__global__ void k_head(const float* __restrict__ Wh, const float* __restrict__ bh,
                       float* __restrict__ out) {
    int g = blockIdx.x;
    int t = threadIdx.x;
    float denom = fmaxf(g_cnt[g], 1.0f);
    float v = (g_pool[g * 128 + t] / denom) * Wh[t];
    __shared__ float sred[4];
#pragma unroll
    for (int off = 16; off > 0; off >>= 1) v += __shfl_down_sync(0xffffffffu, v, off);
    if ((t & 31) == 0) sred[t >> 5] = v;
    __syncthreads();
    if (t == 0) out[g] = sred[0] + sred[1] + sred[2] + sred[3] + bh[0];
}

// ---------------- launch ----------------------------------------------------
extern "C" void kernel_launch(void* const* d_in, const int* in_sizes, int n_in,
                              void* d_out, int out_size) {
    const float* x     = (const float*)d_in[0];
    const int*   ei    = (const int*)d_in[1];
    const int*   batch = (const int*)d_in[2];
    const float* W1    = (const float*)d_in[3];
    const float* as1   = (const float*)d_in[4];
    const float* ad1   = (const float*)d_in[5];
    const float* b1    = (const float*)d_in[6];
    const float* W2    = (const float*)d_in[7];
    const float* as2   = (const float*)d_in[8];
    const float* ad2   = (const float*)d_in[9];
    const float* b2    = (const float*)d_in[10];
    const float* Wh    = (const float*)d_in[11];
    const float* bh    = (const float*)d_in[12];
    float* out = (float*)d_out;

    const int TB = 256;
    int grid_edges = (EP + TB - 1) / TB;
    int grid_nodes = (NN + TB - 1) / TB;
    int grid_gemm  = (NN + 63) / 64;
    int grid_agg   = (NN * 32 + TB - 1) / TB;

    // CSR build (reused by both layers)
    k_zero_init<<<grid_nodes, TB>>>();
    k_hist<<<grid_edges, TB>>>(ei);
    k_scan1<<<NBLK_SCAN, 1024>>>();
    k_scan2<<<1, 64>>>();
    k_scan3<<<grid_nodes, TB>>>();
    k_scatter<<<grid_edges, TB>>>(ei);

    // layer 1
    k_gemm<<<grid_gemm, TB>>>(x, W1, as1, ad1);
    k_agg<0><<<grid_agg, TB>>>(b1, batch);

    // layer 2
    k_gemm<<<grid_gemm, TB>>>(nullptr, W2, as2, ad2);
    k_agg<1><<<grid_agg, TB>>>(b2, batch);

    // head
    k_head<<<NG, 128>>>(Wh, bh, out);
}